// round 1
// baseline (speedup 1.0000x reference)
#include <cuda_runtime.h>

// Problem constants (fixed shapes)
#define B_DIM    4
#define N_NODES  20000
#define K_NB     16
#define IN_DIM_  256
#define C_HID    64
#define H_HEADS  4
#define M_ROWS   (B_DIM * N_NODES)    // 80000
#define OUT_CH   (H_HEADS * C_HID)    // 256

// Scratch (static device globals — no allocations allowed)
__device__ float g_h[(size_t)M_ROWS * OUT_CH];      // 81.9 MB: h = x @ W^T
__device__ float g_Wt[IN_DIM_ * OUT_CH];            // W transposed (k-major)
__device__ float g_ssrc[M_ROWS * H_HEADS];
__device__ float g_sdst[M_ROWS * H_HEADS];

// ---------------------------------------------------------------------------
// Kernel 0: transpose W (256x256) -> Wt[k][n] = W[n][k]
// ---------------------------------------------------------------------------
__global__ void transpose_w_kernel(const float* __restrict__ W) {
    int k = blockIdx.x;      // 0..255
    int n = threadIdx.x;     // 0..255
    g_Wt[k * OUT_CH + n] = W[n * IN_DIM_ + k];
}

// ---------------------------------------------------------------------------
// Kernel 1: GEMM  g_h[M,256] = x[M,256] @ Wt[256,256]
// Classic SIMT fp32 tile: BM=128, BN=128, BK=16, 256 threads, 8x8 per thread
// ---------------------------------------------------------------------------
#define BM 128
#define BN 128
#define BK 16

__global__ __launch_bounds__(256, 2)
void gemm_kernel(const float* __restrict__ A) {
    __shared__ float As[BK][BM + 4];   // transposed store, padded (132 % 4 == 0)
    __shared__ float Bs[BK][BN];

    const int rowBase = blockIdx.y * BM;
    const int colBase = blockIdx.x * BN;
    const int tid = threadIdx.x;
    const int tx = tid & 15;    // col group (8 cols each)
    const int ty = tid >> 4;    // row group (8 rows each)

    float acc[8][8];
#pragma unroll
    for (int i = 0; i < 8; i++)
#pragma unroll
        for (int j = 0; j < 8; j++) acc[i][j] = 0.0f;

    for (int k0 = 0; k0 < IN_DIM_; k0 += BK) {
        // Load A tile: 128 rows x 16 k  = 512 float4, 2 per thread
#pragma unroll
        for (int i = 0; i < 2; i++) {
            int f  = tid * 2 + i;
            int r  = f >> 2;               // 0..127
            int k4 = (f & 3) << 2;         // 0,4,8,12
            float4 v = *(const float4*)&A[(size_t)(rowBase + r) * IN_DIM_ + k0 + k4];
            As[k4 + 0][r] = v.x;
            As[k4 + 1][r] = v.y;
            As[k4 + 2][r] = v.z;
            As[k4 + 3][r] = v.w;
        }
        // Load B tile: 16 k x 128 cols = 512 float4, 2 per thread
#pragma unroll
        for (int i = 0; i < 2; i++) {
            int f  = tid * 2 + i;
            int kk = f >> 5;               // 0..15
            int c4 = (f & 31) << 2;        // 0..124
            *(float4*)&Bs[kk][c4] =
                *(const float4*)&g_Wt[(k0 + kk) * OUT_CH + colBase + c4];
        }
        __syncthreads();

#pragma unroll
        for (int kk = 0; kk < BK; kk++) {
            float4 a0 = *(const float4*)&As[kk][ty * 8];
            float4 a1 = *(const float4*)&As[kk][ty * 8 + 4];
            float4 b0 = *(const float4*)&Bs[kk][tx * 8];
            float4 b1 = *(const float4*)&Bs[kk][tx * 8 + 4];
            float a[8] = {a0.x, a0.y, a0.z, a0.w, a1.x, a1.y, a1.z, a1.w};
            float b[8] = {b0.x, b0.y, b0.z, b0.w, b1.x, b1.y, b1.z, b1.w};
#pragma unroll
            for (int i = 0; i < 8; i++)
#pragma unroll
                for (int j = 0; j < 8; j++) acc[i][j] += a[i] * b[j];
        }
        __syncthreads();
    }

    // Store
#pragma unroll
    for (int i = 0; i < 8; i++) {
        size_t rbase = (size_t)(rowBase + ty * 8 + i) * OUT_CH + colBase + tx * 8;
        *(float4*)&g_h[rbase]     = make_float4(acc[i][0], acc[i][1], acc[i][2], acc[i][3]);
        *(float4*)&g_h[rbase + 4] = make_float4(acc[i][4], acc[i][5], acc[i][6], acc[i][7]);
    }
}

// ---------------------------------------------------------------------------
// Kernel 2: per-row attention scores  s_src[m,h], s_dst[m,h]
// one warp per row
// ---------------------------------------------------------------------------
__global__ void scores_kernel(const float* __restrict__ attn) {
    int gw   = (blockIdx.x * blockDim.x + threadIdx.x) >> 5;  // row
    int lane = threadIdx.x & 31;
    if (gw >= M_ROWS) return;
    const float* hrow = g_h + (size_t)gw * OUT_CH;

#pragma unroll
    for (int hh = 0; hh < H_HEADS; hh++) {
        float v0 = hrow[hh * C_HID + lane];
        float v1 = hrow[hh * C_HID + 32 + lane];
        // attn[h][0:64] = a_src, attn[h][64:128] = a_dst
        float ss = v0 * attn[hh * 128 + lane]      + v1 * attn[hh * 128 + 32 + lane];
        float sd = v0 * attn[hh * 128 + 64 + lane] + v1 * attn[hh * 128 + 96 + lane];
#pragma unroll
        for (int off = 16; off > 0; off >>= 1) {
            ss += __shfl_xor_sync(0xffffffffu, ss, off);
            sd += __shfl_xor_sync(0xffffffffu, sd, off);
        }
        if (lane == 0) {
            g_ssrc[gw * H_HEADS + hh] = ss;
            g_sdst[gw * H_HEADS + hh] = sd;
        }
    }
}

// ---------------------------------------------------------------------------
// Kernel 3: softmax over K neighbors + weighted aggregation
// one warp per row; lane handles output channels (2*lane, 2*lane+1)
// ---------------------------------------------------------------------------
__global__ void agg_kernel(const int* __restrict__ nidx, float* __restrict__ out) {
    int gw   = (blockIdx.x * blockDim.x + threadIdx.x) >> 5;  // row (b*N + n)
    int lane = threadIdx.x & 31;
    if (gw >= M_ROWS) return;

    const int b = gw / N_NODES;
    const int k = lane & 15;                 // lanes 16..31 mirror 0..15
    const int j = nidx[gw * K_NB + k];       // neighbor node within batch b
    const int jr = b * N_NODES + j;          // global gathered row

    const float scale = 0.125f;              // 1/sqrt(C_H)

    float e[H_HEADS];
#pragma unroll
    for (int hh = 0; hh < H_HEADS; hh++) {
        float ss = g_ssrc[gw * H_HEADS + hh];
        float sd = g_sdst[jr * H_HEADS + hh];
        e[hh] = (ss + sd) * scale;
    }

    // softmax over the 16-lane group (halves are identical, xor<=8 stays in-group)
    float alpha[H_HEADS];
#pragma unroll
    for (int hh = 0; hh < H_HEADS; hh++) {
        float m = e[hh];
#pragma unroll
        for (int off = 8; off > 0; off >>= 1)
            m = fmaxf(m, __shfl_xor_sync(0xffffffffu, m, off));
        float ex = __expf(e[hh] - m);
        float s = ex;
#pragma unroll
        for (int off = 8; off > 0; off >>= 1)
            s += __shfl_xor_sync(0xffffffffu, s, off);
        alpha[hh] = ex / s;
    }

    // Weighted gather-accumulate: out[c] = 0.25 * sum_h sum_k alpha[k,h]*h[j_k, h*64+c]
    float acc0 = 0.0f, acc1 = 0.0f;
    const size_t base_b = (size_t)b * N_NODES;

#pragma unroll 4
    for (int kk = 0; kk < K_NB; kk++) {
        int jj = __shfl_sync(0xffffffffu, j, kk);
        float w[H_HEADS];
#pragma unroll
        for (int hh = 0; hh < H_HEADS; hh++)
            w[hh] = __shfl_sync(0xffffffffu, alpha[hh], kk);

        const float2* hp = (const float2*)g_h + (base_b + (size_t)jj) * (OUT_CH / 2);
#pragma unroll
        for (int hh = 0; hh < H_HEADS; hh++) {
            float2 v = hp[hh * 32 + lane];   // channels (2*lane, 2*lane+1) of head hh
            acc0 += w[hh] * v.x;
            acc1 += w[hh] * v.y;
        }
    }

    float2 o;
    o.x = acc0 * 0.25f;   // mean over H=4 heads
    o.y = acc1 * 0.25f;
    ((float2*)out)[(size_t)gw * (C_HID / 2) + lane] = o;
}

// ---------------------------------------------------------------------------
// Launch
// ---------------------------------------------------------------------------
extern "C" void kernel_launch(void* const* d_in, const int* in_sizes, int n_in,
                              void* d_out, int out_size) {
    const float* x    = (const float*)d_in[0];   // (4,20000,256) f32
    const int*   nidx = (const int*)d_in[1];     // (4,20000,16)  i32
    const float* W    = (const float*)d_in[2];   // (256,256)     f32
    const float* attn = (const float*)d_in[3];   // (4,128)       f32
    float* out = (float*)d_out;                  // (4,20000,64)  f32

    transpose_w_kernel<<<IN_DIM_, OUT_CH>>>(W);
    gemm_kernel<<<dim3(OUT_CH / BN, M_ROWS / BM), 256>>>(x);

    // 80000 rows, 1 warp each, 8 warps/block -> 10000 blocks exactly
    scores_kernel<<<M_ROWS / 8, 256>>>(attn);
    agg_kernel<<<M_ROWS / 8, 256>>>(nidx, out);
}

// round 4
// speedup vs baseline: 1.9520x; 1.9520x over previous
#include <cuda_runtime.h>
#include <cuda_fp16.h>
#include <cstdint>

// -------------------- problem constants --------------------
#define B_DIM    4
#define N_NODES  20000
#define K_NB     16
#define IN_DIM_  256
#define C_HID    64
#define H_HEADS  4
#define M_ROWS   (B_DIM * N_NODES)     // 80000
#define OUT_CH   256                   // H*C_H

// -------------------- scratch (static, no allocs) --------------------
__device__ __half g_h16[(size_t)M_ROWS * OUT_CH];    // 41 MB: h in fp16
__device__ __half g_x16[(size_t)M_ROWS * IN_DIM_];   // 41 MB: x in fp16
__device__ __half g_W16[2][OUT_CH][IN_DIM_];         // W hi/lo fp16 split
__device__ float  g_uv[8][IN_DIM_];                  // folded attn vecs: [h]=src, [4+h]=dst
__device__ float  g_ssrc[M_ROWS * H_HEADS];
__device__ float  g_sdst[M_ROWS * H_HEADS];

// -------------------- asm helpers (sm_100-safe, no 'a' features) ----------
__device__ __forceinline__ uint32_t smem_u32(const void* p) {
    uint32_t a;
    asm("{ .reg .u64 t; cvta.to.shared.u64 t, %1; cvt.u32.u64 %0, t; }" : "=r"(a) : "l"(p));
    return a;
}
#define CP_ASYNC16(saddr, gptr) \
    asm volatile("{ .reg .u64 g; cvta.to.global.u64 g, %1; cp.async.cg.shared.global [%0], [g], 16; }" \
        :: "r"(saddr), "l"(gptr) : "memory")
#define CP_COMMIT() asm volatile("cp.async.commit_group;" ::: "memory")
#define CP_WAIT1()  asm volatile("cp.async.wait_group 1;" ::: "memory")
#define LDMX4(r0, r1, r2, r3, addr) \
    asm volatile("ldmatrix.sync.aligned.m8n8.x4.shared.b16 {%0,%1,%2,%3}, [%4];" \
        : "=r"(r0), "=r"(r1), "=r"(r2), "=r"(r3) : "r"(addr))
#define MMA16816(d, a, b) \
    asm volatile("mma.sync.aligned.m16n8k16.row.col.f32.f16.f16.f32 " \
        "{%0,%1,%2,%3},{%4,%5,%6,%7},{%8,%9},{%0,%1,%2,%3};" \
        : "+f"((d)[0]), "+f"((d)[1]), "+f"((d)[2]), "+f"((d)[3]) \
        : "r"((a)[0]), "r"((a)[1]), "r"((a)[2]), "r"((a)[3]), "r"((b)[0]), "r"((b)[1]))

// ---------------------------------------------------------------------------
// Kernel A: fold attn into W: u[h][k] = sum_c W[h*64+c][k]*a_src[h][c] (t<4),
//           v likewise with a_dst (t>=4). grid 8, block 256.
// ---------------------------------------------------------------------------
__global__ void uv_kernel(const float* __restrict__ W, const float* __restrict__ attn) {
    int t = blockIdx.x;          // 0..7
    int h = t & 3, side = t >> 2;
    int k = threadIdx.x;         // 0..255
    float acc = 0.f;
#pragma unroll 8
    for (int c = 0; c < C_HID; c++)
        acc += W[(h * C_HID + c) * IN_DIM_ + k] * __ldg(&attn[h * 128 + side * C_HID + c]);
    g_uv[t][k] = acc;
}

// ---------------------------------------------------------------------------
// Kernel B: W -> fp16 hi/lo split
// ---------------------------------------------------------------------------
__global__ void w16_kernel(const float* __restrict__ W) {
    int n = blockIdx.x, k = threadIdx.x;
    float v = W[n * IN_DIM_ + k];
    __half hi = __float2half_rn(v);
    __half lo = __float2half_rn(v - __half2float(hi));
    g_W16[0][n][k] = hi;
    g_W16[1][n][k] = lo;
}

// ---------------------------------------------------------------------------
// Kernel C: x -> fp16 + fused attention scores (s = x . uv[t])
// grid 625, block 256 (8 warps); each warp: 16 rows; lane owns k = lane*8..+7
// ---------------------------------------------------------------------------
__global__ __launch_bounds__(256)
void xprep_kernel(const float* __restrict__ x) {
    const int tid = threadIdx.x, lane = tid & 31, wid = tid >> 5;

    // per-lane uv slice in registers (k = lane*8 .. +7), 64 floats
    float uvr[8][8];
#pragma unroll
    for (int t = 0; t < 8; t++) {
        float4 a = *(const float4*)&g_uv[t][lane * 8];
        float4 b = *(const float4*)&g_uv[t][lane * 8 + 4];
        uvr[t][0] = a.x; uvr[t][1] = a.y; uvr[t][2] = a.z; uvr[t][3] = a.w;
        uvr[t][4] = b.x; uvr[t][5] = b.y; uvr[t][6] = b.z; uvr[t][7] = b.w;
    }

    const int rowBase = (blockIdx.x * 8 + wid) * 16;
#pragma unroll 2
    for (int r = 0; r < 16; r++) {
        const int row = rowBase + r;
        const float4* xp = (const float4*)(x + (size_t)row * IN_DIM_) + lane * 2;
        float4 v0 = xp[0], v1 = xp[1];
        float xv[8] = {v0.x, v0.y, v0.z, v0.w, v1.x, v1.y, v1.z, v1.w};

        // store fp16
        __half hh[8];
#pragma unroll
        for (int i = 0; i < 8; i++) hh[i] = __float2half_rn(xv[i]);
        *(uint4*)(g_x16 + (size_t)row * IN_DIM_ + lane * 8) = *(uint4*)hh;

        // 8 score dots
        float acc[8];
#pragma unroll
        for (int t = 0; t < 8; t++) {
            float s = 0.f;
#pragma unroll
            for (int i = 0; i < 8; i++) s = fmaf(xv[i], uvr[t][i], s);
            acc[t] = s;
        }
#pragma unroll
        for (int t = 0; t < 8; t++) {
#pragma unroll
            for (int off = 16; off > 0; off >>= 1)
                acc[t] += __shfl_xor_sync(0xffffffffu, acc[t], off);
        }
        if (lane == 0) {
            *(float4*)&g_ssrc[row * H_HEADS] = make_float4(acc[0], acc[1], acc[2], acc[3]);
            *(float4*)&g_sdst[row * H_HEADS] = make_float4(acc[4], acc[5], acc[6], acc[7]);
        }
    }
}

// ---------------------------------------------------------------------------
// Kernel D: GEMM h16 = fp16(x) @ (Wh + Wl)^T via mma.sync m16n8k16
// CTA tile 128(M) x 64(N); W both splits resident in smem (64KB),
// A triple-buffered 32-k chunks via cp.async. 8 warps: 4(M) x 2(N), warp 32x32.
// grid (4, 625); 2 CTAs/SM.
// ---------------------------------------------------------------------------
#define GSM_B_BYTES   65536          // 2 splits * 64 n * 512 B
#define GSM_A_STAGE   8192           // 128 m * 64 B
#define GSM_TOTAL     (GSM_B_BYTES + 3 * GSM_A_STAGE)   // 90112

__global__ __launch_bounds__(256, 2)
void gemm_kernel() {
    extern __shared__ char smem[];
    const uint32_t Bq = smem_u32(smem);
    const uint32_t Aq = Bq + GSM_B_BYTES;

    const int tid = threadIdx.x, lane = tid & 31, wid = tid >> 5;
    const int mBase = blockIdx.y * 128;
    const int nBase = blockIdx.x * 64;
    const int wm = wid >> 1;      // 0..3 (32 rows each)
    const int wn = wid & 1;       // 0..1 (32 cols each)

    // ---- B: load both W splits for this n-half (4096 x 16B chunks)
    {
        const __half* Wb = &g_W16[0][0][0];
#pragma unroll
        for (int i = 0; i < 16; i++) {
            int cid = i * 256 + tid;
            int split = cid >> 11;            // 2048 chunks per split
            int n = (cid >> 5) & 63;
            int c = cid & 31;
            const __half* g = Wb + (size_t)split * OUT_CH * IN_DIM_
                                 + (size_t)(nBase + n) * IN_DIM_ + c * 8;
            uint32_t s = Bq + split * 32768 + n * 512 + ((c ^ (n & 7)) << 4);
            CP_ASYNC16(s, g);
        }
        CP_COMMIT();
    }
    // ---- A stage loader (32 k per stage, 512 x 16B chunks)
    auto loadA = [&](int kc) {
        uint32_t Ast = Aq + (kc % 3) * GSM_A_STAGE;
#pragma unroll
        for (int i = 0; i < 2; i++) {
            int cid = i * 256 + tid;
            int m = cid >> 2, c = cid & 3;
            const __half* g = g_x16 + (size_t)(mBase + m) * IN_DIM_ + kc * 32 + c * 8;
            uint32_t s = Ast + m * 64 + ((c ^ ((m >> 1) & 3)) << 4);
            CP_ASYNC16(s, g);
        }
        CP_COMMIT();
    };
    loadA(0);
    loadA(1);
    CP_WAIT1();          // B + A0 complete (A1 may be in flight)
    __syncthreads();

    float acc[2][4][4];
#pragma unroll
    for (int mi = 0; mi < 2; mi++)
#pragma unroll
        for (int ni = 0; ni < 4; ni++)
#pragma unroll
            for (int q = 0; q < 4; q++) acc[mi][ni][q] = 0.f;

    for (int kc = 0; kc < 8; kc++) {
        const uint32_t Ast = Aq + (kc % 3) * GSM_A_STAGE;
#pragma unroll
        for (int s = 0; s < 2; s++) {          // two k16 steps per 32-k chunk
            uint32_t a[2][4];
#pragma unroll
            for (int mi = 0; mi < 2; mi++) {
                int row = wm * 32 + mi * 16 + (lane & 15);
                int c = s * 2 + (lane >> 4);
                uint32_t ad = Ast + row * 64 + ((c ^ ((row >> 1) & 3)) << 4);
                LDMX4(a[mi][0], a[mi][1], a[mi][2], a[mi][3], ad);
            }
#pragma unroll
            for (int sp = 0; sp < 2; sp++) {   // W hi / lo split
                uint32_t b[4][2];
#pragma unroll
                for (int bi = 0; bi < 2; bi++) {
                    int nrow = wn * 32 + bi * 16 + (lane & 15);
                    int c = kc * 4 + s * 2 + (lane >> 4);
                    uint32_t ad = Bq + sp * 32768 + nrow * 512 + ((c ^ (nrow & 7)) << 4);
                    uint32_t r0, r1, r2, r3;
                    LDMX4(r0, r1, r2, r3, ad);
                    b[bi * 2 + 0][0] = r0; b[bi * 2 + 0][1] = r2;
                    b[bi * 2 + 1][0] = r1; b[bi * 2 + 1][1] = r3;
                }
#pragma unroll
                for (int mi = 0; mi < 2; mi++)
#pragma unroll
                    for (int ni = 0; ni < 4; ni++)
                        MMA16816(acc[mi][ni], a[mi], b[ni]);
            }
        }
        if (kc < 6) loadA(kc + 2); else CP_COMMIT();   // keep group cadence
        if (kc < 7) { CP_WAIT1(); __syncthreads(); }
    }

    // ---- epilogue: fp32 acc -> fp16 h
#pragma unroll
    for (int mi = 0; mi < 2; mi++)
#pragma unroll
        for (int ni = 0; ni < 4; ni++) {
            int row0 = mBase + wm * 32 + mi * 16 + (lane >> 2);
            int col  = nBase + wn * 32 + ni * 8 + (lane & 3) * 2;
            __half2 v0 = __floats2half2_rn(acc[mi][ni][0], acc[mi][ni][1]);
            __half2 v1 = __floats2half2_rn(acc[mi][ni][2], acc[mi][ni][3]);
            *(__half2*)&g_h16[(size_t)row0 * OUT_CH + col] = v0;
            *(__half2*)&g_h16[(size_t)(row0 + 8) * OUT_CH + col] = v1;
        }
}

// ---------------------------------------------------------------------------
// Kernel E: softmax over K neighbors + weighted aggregation (one warp / row)
// ---------------------------------------------------------------------------
__global__ void agg_kernel(const int* __restrict__ nidx, float* __restrict__ out) {
    int gw   = (blockIdx.x * blockDim.x + threadIdx.x) >> 5;
    int lane = threadIdx.x & 31;
    if (gw >= M_ROWS) return;

    const int b = gw / N_NODES;
    const int k = lane & 15;
    const int j = __ldg(&nidx[gw * K_NB + k]);
    const int jr = b * N_NODES + j;

    const float scale = 0.125f;

    float e[H_HEADS];
#pragma unroll
    for (int hh = 0; hh < H_HEADS; hh++) {
        float ssv = g_ssrc[gw * H_HEADS + hh];
        float sdv = g_sdst[jr * H_HEADS + hh];
        e[hh] = (ssv + sdv) * scale;
    }

    float alpha[H_HEADS];
#pragma unroll
    for (int hh = 0; hh < H_HEADS; hh++) {
        float m = e[hh];
#pragma unroll
        for (int off = 8; off > 0; off >>= 1)
            m = fmaxf(m, __shfl_xor_sync(0xffffffffu, m, off));
        float ex = __expf(e[hh] - m);
        float s = ex;
#pragma unroll
        for (int off = 8; off > 0; off >>= 1)
            s += __shfl_xor_sync(0xffffffffu, s, off);
        alpha[hh] = ex / s;
    }

    float acc0 = 0.0f, acc1 = 0.0f;
    const size_t base_b = (size_t)b * N_NODES;

#pragma unroll 4
    for (int kk = 0; kk < K_NB; kk++) {
        int jj = __shfl_sync(0xffffffffu, j, kk);
        float w[H_HEADS];
#pragma unroll
        for (int hh = 0; hh < H_HEADS; hh++)
            w[hh] = __shfl_sync(0xffffffffu, alpha[hh], kk);

        const __half2* hp = (const __half2*)g_h16 + (base_b + (size_t)jj) * (OUT_CH / 2);
#pragma unroll
        for (int hh = 0; hh < H_HEADS; hh++) {
            float2 v = __half22float2(hp[hh * 32 + lane]);
            acc0 = fmaf(w[hh], v.x, acc0);
            acc1 = fmaf(w[hh], v.y, acc1);
        }
    }

    float2 o;
    o.x = acc0 * 0.25f;
    o.y = acc1 * 0.25f;
    ((float2*)out)[(size_t)gw * (C_HID / 2) + lane] = o;
}

// ---------------------------------------------------------------------------
extern "C" void kernel_launch(void* const* d_in, const int* in_sizes, int n_in,
                              void* d_out, int out_size) {
    const float* x    = (const float*)d_in[0];
    const int*   nidx = (const int*)d_in[1];
    const float* W    = (const float*)d_in[2];
    const float* attn = (const float*)d_in[3];
    float* out = (float*)d_out;

    cudaFuncSetAttribute(gemm_kernel, cudaFuncAttributeMaxDynamicSharedMemorySize, GSM_TOTAL);

    uv_kernel<<<8, 256>>>(W, attn);
    w16_kernel<<<OUT_CH, IN_DIM_>>>(W);
    xprep_kernel<<<M_ROWS / 128, 256>>>(x);
    gemm_kernel<<<dim3(4, M_ROWS / 128), 256, GSM_TOTAL>>>();
    agg_kernel<<<M_ROWS / 8, 256>>>(nidx, out);
}

// round 5
// speedup vs baseline: 2.2471x; 1.1512x over previous
#include <cuda_runtime.h>
#include <cuda_fp16.h>
#include <cstdint>

// -------------------- problem constants --------------------
#define B_DIM    4
#define N_NODES  20000
#define K_NB     16
#define IN_DIM_  256
#define C_HID    64
#define H_HEADS  4
#define M_ROWS   (B_DIM * N_NODES)     // 80000
#define OUT_CH   256                   // H*C_H

// -------------------- scratch (static, no allocs) --------------------
__device__ __half g_h16[(size_t)M_ROWS * OUT_CH];    // 41 MB: h in fp16
__device__ __half g_x16[(size_t)M_ROWS * IN_DIM_];   // 41 MB: x in fp16
__device__ __half g_W16[OUT_CH][IN_DIM_];            // W fp16 (single)
__device__ float  g_uv[8][IN_DIM_];                  // folded attn vecs: [h]=src, [4+h]=dst
__device__ float  g_ssrc[M_ROWS * H_HEADS];
__device__ float  g_sdst[M_ROWS * H_HEADS];

// -------------------- asm helpers (sm_100-safe, no 'a' features) ----------
__device__ __forceinline__ uint32_t smem_u32(const void* p) {
    uint32_t a;
    asm("{ .reg .u64 t; cvta.to.shared.u64 t, %1; cvt.u32.u64 %0, t; }" : "=r"(a) : "l"(p));
    return a;
}
#define CP_ASYNC16(saddr, gptr) \
    asm volatile("{ .reg .u64 g; cvta.to.global.u64 g, %1; cp.async.cg.shared.global [%0], [g], 16; }" \
        :: "r"(saddr), "l"(gptr) : "memory")
#define CP_COMMIT() asm volatile("cp.async.commit_group;" ::: "memory")
#define CP_WAIT1()  asm volatile("cp.async.wait_group 1;" ::: "memory")
#define LDMX4(r0, r1, r2, r3, addr) \
    asm volatile("ldmatrix.sync.aligned.m8n8.x4.shared.b16 {%0,%1,%2,%3}, [%4];" \
        : "=r"(r0), "=r"(r1), "=r"(r2), "=r"(r3) : "r"(addr))
#define MMA16816(d, a, b) \
    asm volatile("mma.sync.aligned.m16n8k16.row.col.f32.f16.f16.f32 " \
        "{%0,%1,%2,%3},{%4,%5,%6,%7},{%8,%9},{%0,%1,%2,%3};" \
        : "+f"((d)[0]), "+f"((d)[1]), "+f"((d)[2]), "+f"((d)[3]) \
        : "r"((a)[0]), "r"((a)[1]), "r"((a)[2]), "r"((a)[3]), "r"((b)[0]), "r"((b)[1]))

// ---------------------------------------------------------------------------
// Kernel A: fold attn into W: u[t][k], t<4 -> a_src, t>=4 -> a_dst
// ---------------------------------------------------------------------------
__global__ void uv_kernel(const float* __restrict__ W, const float* __restrict__ attn) {
    int t = blockIdx.x;          // 0..7
    int h = t & 3, side = t >> 2;
    int k = threadIdx.x;         // 0..255
    float acc = 0.f;
#pragma unroll 8
    for (int c = 0; c < C_HID; c++)
        acc += W[(h * C_HID + c) * IN_DIM_ + k] * __ldg(&attn[h * 128 + side * C_HID + c]);
    g_uv[t][k] = acc;
}

// ---------------------------------------------------------------------------
// Kernel B: W -> fp16
// ---------------------------------------------------------------------------
__global__ void w16_kernel(const float* __restrict__ W) {
    int n = blockIdx.x, k = threadIdx.x;
    g_W16[n][k] = __float2half_rn(W[n * IN_DIM_ + k]);
}

// ---------------------------------------------------------------------------
// Kernel C: x -> fp16 + fused attention scores (s = x . uv[t])
// ---------------------------------------------------------------------------
__global__ __launch_bounds__(256)
void xprep_kernel(const float* __restrict__ x) {
    const int tid = threadIdx.x, lane = tid & 31, wid = tid >> 5;

    float uvr[8][8];
#pragma unroll
    for (int t = 0; t < 8; t++) {
        float4 a = *(const float4*)&g_uv[t][lane * 8];
        float4 b = *(const float4*)&g_uv[t][lane * 8 + 4];
        uvr[t][0] = a.x; uvr[t][1] = a.y; uvr[t][2] = a.z; uvr[t][3] = a.w;
        uvr[t][4] = b.x; uvr[t][5] = b.y; uvr[t][6] = b.z; uvr[t][7] = b.w;
    }

    const int rowBase = (blockIdx.x * 8 + wid) * 16;
#pragma unroll 2
    for (int r = 0; r < 16; r++) {
        const int row = rowBase + r;
        const float4* xp = (const float4*)(x + (size_t)row * IN_DIM_) + lane * 2;
        float4 v0 = xp[0], v1 = xp[1];
        float xv[8] = {v0.x, v0.y, v0.z, v0.w, v1.x, v1.y, v1.z, v1.w};

        __half hh[8];
#pragma unroll
        for (int i = 0; i < 8; i++) hh[i] = __float2half_rn(xv[i]);
        *(uint4*)(g_x16 + (size_t)row * IN_DIM_ + lane * 8) = *(uint4*)hh;

        float acc[8];
#pragma unroll
        for (int t = 0; t < 8; t++) {
            float s = 0.f;
#pragma unroll
            for (int i = 0; i < 8; i++) s = fmaf(xv[i], uvr[t][i], s);
            acc[t] = s;
        }
#pragma unroll
        for (int t = 0; t < 8; t++) {
#pragma unroll
            for (int off = 16; off > 0; off >>= 1)
                acc[t] += __shfl_xor_sync(0xffffffffu, acc[t], off);
        }
        if (lane == 0) {
            *(float4*)&g_ssrc[row * H_HEADS] = make_float4(acc[0], acc[1], acc[2], acc[3]);
            *(float4*)&g_sdst[row * H_HEADS] = make_float4(acc[4], acc[5], acc[6], acc[7]);
        }
    }
}

// ---------------------------------------------------------------------------
// Kernel D: GEMM h16 = fp16(x) @ W16^T via mma.sync m16n8k16 (single split)
// CTA tile 128(M) x 64(N); W half (32KB) resident, A triple-buffered.
// 8 warps: 4(M) x 2(N), warp 32x32. grid (4, 625); 3 CTAs/SM.
// ---------------------------------------------------------------------------
#define GSM_B_BYTES   32768          // 64 n * 512 B
#define GSM_A_STAGE   8192           // 128 m * 64 B
#define GSM_TOTAL     (GSM_B_BYTES + 3 * GSM_A_STAGE)   // 57344

__global__ __launch_bounds__(256, 3)
void gemm_kernel() {
    extern __shared__ char smem[];
    const uint32_t Bq = smem_u32(smem);
    const uint32_t Aq = Bq + GSM_B_BYTES;

    const int tid = threadIdx.x, lane = tid & 31, wid = tid >> 5;
    const int mBase = blockIdx.y * 128;
    const int nBase = blockIdx.x * 64;
    const int wm = wid >> 1;      // 0..3 (32 rows each)
    const int wn = wid & 1;       // 0..1 (32 cols each)

    // ---- B: load W n-slice (2048 x 16B chunks)
    {
#pragma unroll
        for (int i = 0; i < 8; i++) {
            int cid = i * 256 + tid;
            int n = cid >> 5;
            int c = cid & 31;
            const __half* g = &g_W16[nBase + n][c * 8];
            uint32_t s = Bq + n * 512 + ((c ^ (n & 7)) << 4);
            CP_ASYNC16(s, g);
        }
        CP_COMMIT();
    }
    // ---- A stage loader (32 k per stage, 512 x 16B chunks)
    auto loadA = [&](int kc) {
        uint32_t Ast = Aq + (kc % 3) * GSM_A_STAGE;
#pragma unroll
        for (int i = 0; i < 2; i++) {
            int cid = i * 256 + tid;
            int m = cid >> 2, c = cid & 3;
            const __half* g = g_x16 + (size_t)(mBase + m) * IN_DIM_ + kc * 32 + c * 8;
            uint32_t s = Ast + m * 64 + ((c ^ ((m >> 1) & 3)) << 4);
            CP_ASYNC16(s, g);
        }
        CP_COMMIT();
    };
    loadA(0);
    loadA(1);
    CP_WAIT1();          // B + A0 complete
    __syncthreads();

    float acc[2][4][4];
#pragma unroll
    for (int mi = 0; mi < 2; mi++)
#pragma unroll
        for (int ni = 0; ni < 4; ni++)
#pragma unroll
            for (int q = 0; q < 4; q++) acc[mi][ni][q] = 0.f;

    for (int kc = 0; kc < 8; kc++) {
        const uint32_t Ast = Aq + (kc % 3) * GSM_A_STAGE;
#pragma unroll
        for (int s = 0; s < 2; s++) {          // two k16 steps per 32-k chunk
            uint32_t a[2][4];
#pragma unroll
            for (int mi = 0; mi < 2; mi++) {
                int row = wm * 32 + mi * 16 + (lane & 15);
                int c = s * 2 + (lane >> 4);
                uint32_t ad = Ast + row * 64 + ((c ^ ((row >> 1) & 3)) << 4);
                LDMX4(a[mi][0], a[mi][1], a[mi][2], a[mi][3], ad);
            }
            uint32_t b[4][2];
#pragma unroll
            for (int bi = 0; bi < 2; bi++) {
                int nrow = wn * 32 + bi * 16 + (lane & 15);
                int c = kc * 4 + s * 2 + (lane >> 4);
                uint32_t ad = Bq + nrow * 512 + ((c ^ (nrow & 7)) << 4);
                uint32_t r0, r1, r2, r3;
                LDMX4(r0, r1, r2, r3, ad);
                b[bi * 2 + 0][0] = r0; b[bi * 2 + 0][1] = r2;
                b[bi * 2 + 1][0] = r1; b[bi * 2 + 1][1] = r3;
            }
#pragma unroll
            for (int mi = 0; mi < 2; mi++)
#pragma unroll
                for (int ni = 0; ni < 4; ni++)
                    MMA16816(acc[mi][ni], a[mi], b[ni]);
        }
        if (kc < 6) loadA(kc + 2); else CP_COMMIT();
        if (kc < 7) { CP_WAIT1(); __syncthreads(); }
    }

    // ---- epilogue: fp32 acc -> fp16 h
#pragma unroll
    for (int mi = 0; mi < 2; mi++)
#pragma unroll
        for (int ni = 0; ni < 4; ni++) {
            int row0 = mBase + wm * 32 + mi * 16 + (lane >> 2);
            int col  = nBase + wn * 32 + ni * 8 + (lane & 3) * 2;
            __half2 v0 = __floats2half2_rn(acc[mi][ni][0], acc[mi][ni][1]);
            __half2 v1 = __floats2half2_rn(acc[mi][ni][2], acc[mi][ni][3]);
            *(__half2*)&g_h16[(size_t)row0 * OUT_CH + col] = v0;
            *(__half2*)&g_h16[(size_t)(row0 + 8) * OUT_CH + col] = v1;
        }
}

// ---------------------------------------------------------------------------
// Kernel E: softmax over K neighbors + weighted aggregation (one warp / row)
// ---------------------------------------------------------------------------
__global__ void agg_kernel(const int* __restrict__ nidx, float* __restrict__ out) {
    int gw   = (blockIdx.x * blockDim.x + threadIdx.x) >> 5;
    int lane = threadIdx.x & 31;
    if (gw >= M_ROWS) return;

    const int b = gw / N_NODES;
    const int k = lane & 15;
    const int j = __ldg(&nidx[gw * K_NB + k]);
    const int jr = b * N_NODES + j;

    const float scale = 0.125f;

    float e[H_HEADS];
#pragma unroll
    for (int hh = 0; hh < H_HEADS; hh++) {
        float ssv = g_ssrc[gw * H_HEADS + hh];
        float sdv = g_sdst[jr * H_HEADS + hh];
        e[hh] = (ssv + sdv) * scale;
    }

    float alpha[H_HEADS];
#pragma unroll
    for (int hh = 0; hh < H_HEADS; hh++) {
        float m = e[hh];
#pragma unroll
        for (int off = 8; off > 0; off >>= 1)
            m = fmaxf(m, __shfl_xor_sync(0xffffffffu, m, off));
        float ex = __expf(e[hh] - m);
        float s = ex;
#pragma unroll
        for (int off = 8; off > 0; off >>= 1)
            s += __shfl_xor_sync(0xffffffffu, s, off);
        alpha[hh] = ex / s;
    }

    float acc0 = 0.0f, acc1 = 0.0f;
    const size_t base_b = (size_t)b * N_NODES;

#pragma unroll 4
    for (int kk = 0; kk < K_NB; kk++) {
        int jj = __shfl_sync(0xffffffffu, j, kk);
        float w[H_HEADS];
#pragma unroll
        for (int hh = 0; hh < H_HEADS; hh++)
            w[hh] = __shfl_sync(0xffffffffu, alpha[hh], kk);

        const __half2* hp = (const __half2*)g_h16 + (base_b + (size_t)jj) * (OUT_CH / 2);
#pragma unroll
        for (int hh = 0; hh < H_HEADS; hh++) {
            float2 v = __half22float2(hp[hh * 32 + lane]);
            acc0 = fmaf(w[hh], v.x, acc0);
            acc1 = fmaf(w[hh], v.y, acc1);
        }
    }

    float2 o;
    o.x = acc0 * 0.25f;
    o.y = acc1 * 0.25f;
    ((float2*)out)[(size_t)gw * (C_HID / 2) + lane] = o;
}

// ---------------------------------------------------------------------------
extern "C" void kernel_launch(void* const* d_in, const int* in_sizes, int n_in,
                              void* d_out, int out_size) {
    const float* x    = (const float*)d_in[0];
    const int*   nidx = (const int*)d_in[1];
    const float* W    = (const float*)d_in[2];
    const float* attn = (const float*)d_in[3];
    float* out = (float*)d_out;

    cudaFuncSetAttribute(gemm_kernel, cudaFuncAttributeMaxDynamicSharedMemorySize, GSM_TOTAL);

    uv_kernel<<<8, 256>>>(W, attn);
    w16_kernel<<<OUT_CH, IN_DIM_>>>(W);
    xprep_kernel<<<M_ROWS / 128, 256>>>(x);
    gemm_kernel<<<dim3(4, M_ROWS / 128), 256, GSM_TOTAL>>>();
    agg_kernel<<<M_ROWS / 8, 256>>>(nidx, out);
}

// round 7
// speedup vs baseline: 2.4462x; 1.0886x over previous
#include <cuda_runtime.h>
#include <cuda_fp16.h>
#include <cstdint>

// -------------------- problem constants --------------------
#define B_DIM    4
#define N_NODES  20000
#define K_NB     16
#define IN_DIM_  256
#define C_HID    64
#define H_HEADS  4
#define M_ROWS   (B_DIM * N_NODES)     // 80000
#define OUT_CH   256                   // H*C_H

// -------------------- scratch (static, no allocs) --------------------
__device__ __half g_h16[(size_t)M_ROWS * OUT_CH];    // 41 MB: h in fp16
__device__ __half g_x16[(size_t)M_ROWS * IN_DIM_];   // 41 MB: x in fp16
__device__ __half g_W16[OUT_CH][IN_DIM_];            // W fp16
__device__ float  g_uv[8][IN_DIM_];                  // folded attn vecs
__device__ float  g_ssrc[M_ROWS * H_HEADS];
__device__ float  g_sdst[M_ROWS * H_HEADS];

// -------------------- asm helpers (sm_100-safe) ----------
__device__ __forceinline__ uint32_t smem_u32(const void* p) {
    uint32_t a;
    asm("{ .reg .u64 t; cvta.to.shared.u64 t, %1; cvt.u32.u64 %0, t; }" : "=r"(a) : "l"(p));
    return a;
}
#define CP_ASYNC16(saddr, gptr) \
    asm volatile("{ .reg .u64 g; cvta.to.global.u64 g, %1; cp.async.cg.shared.global [%0], [g], 16; }" \
        :: "r"(saddr), "l"(gptr) : "memory")
#define CP_COMMIT() asm volatile("cp.async.commit_group;" ::: "memory")
#define CP_WAIT1()  asm volatile("cp.async.wait_group 1;" ::: "memory")
#define LDMX4(r0, r1, r2, r3, addr) \
    asm volatile("ldmatrix.sync.aligned.m8n8.x4.shared.b16 {%0,%1,%2,%3}, [%4];" \
        : "=r"(r0), "=r"(r1), "=r"(r2), "=r"(r3) : "r"(addr))
#define MMA16816(d, a, b) \
    asm volatile("mma.sync.aligned.m16n8k16.row.col.f32.f16.f16.f32 " \
        "{%0,%1,%2,%3},{%4,%5,%6,%7},{%8,%9},{%0,%1,%2,%3};" \
        : "+f"((d)[0]), "+f"((d)[1]), "+f"((d)[2]), "+f"((d)[3]) \
        : "r"((a)[0]), "r"((a)[1]), "r"((a)[2]), "r"((a)[3]), "r"((b)[0]), "r"((b)[1]))

// ---------------------------------------------------------------------------
// Kernel A: fold attn into W
// ---------------------------------------------------------------------------
__global__ void uv_kernel(const float* __restrict__ W, const float* __restrict__ attn) {
    int t = blockIdx.x;
    int h = t & 3, side = t >> 2;
    int k = threadIdx.x;
    float acc = 0.f;
#pragma unroll 8
    for (int c = 0; c < C_HID; c++)
        acc += W[(h * C_HID + c) * IN_DIM_ + k] * __ldg(&attn[h * 128 + side * C_HID + c]);
    g_uv[t][k] = acc;
}

// ---------------------------------------------------------------------------
// Kernel B: W -> fp16
// ---------------------------------------------------------------------------
__global__ void w16_kernel(const float* __restrict__ W) {
    int n = blockIdx.x, k = threadIdx.x;
    g_W16[n][k] = __float2half_rn(W[n * IN_DIM_ + k]);
}

// ---------------------------------------------------------------------------
// Kernel C: x -> fp16 + fused attention scores
// ---------------------------------------------------------------------------
__global__ __launch_bounds__(256)
void xprep_kernel(const float* __restrict__ x) {
    const int tid = threadIdx.x, lane = tid & 31, wid = tid >> 5;

    float uvr[8][8];
#pragma unroll
    for (int t = 0; t < 8; t++) {
        float4 a = *(const float4*)&g_uv[t][lane * 8];
        float4 b = *(const float4*)&g_uv[t][lane * 8 + 4];
        uvr[t][0] = a.x; uvr[t][1] = a.y; uvr[t][2] = a.z; uvr[t][3] = a.w;
        uvr[t][4] = b.x; uvr[t][5] = b.y; uvr[t][6] = b.z; uvr[t][7] = b.w;
    }

    const int rowBase = (blockIdx.x * 8 + wid) * 16;
#pragma unroll 2
    for (int r = 0; r < 16; r++) {
        const int row = rowBase + r;
        const float4* xp = (const float4*)(x + (size_t)row * IN_DIM_) + lane * 2;
        float4 v0 = xp[0], v1 = xp[1];
        float xv[8] = {v0.x, v0.y, v0.z, v0.w, v1.x, v1.y, v1.z, v1.w};

        __half hh[8];
#pragma unroll
        for (int i = 0; i < 8; i++) hh[i] = __float2half_rn(xv[i]);
        *(uint4*)(g_x16 + (size_t)row * IN_DIM_ + lane * 8) = *(uint4*)hh;

        float acc[8];
#pragma unroll
        for (int t = 0; t < 8; t++) {
            float s = 0.f;
#pragma unroll
            for (int i = 0; i < 8; i++) s = fmaf(xv[i], uvr[t][i], s);
            acc[t] = s;
        }
#pragma unroll
        for (int t = 0; t < 8; t++) {
#pragma unroll
            for (int off = 16; off > 0; off >>= 1)
                acc[t] += __shfl_xor_sync(0xffffffffu, acc[t], off);
        }
        if (lane == 0) {
            *(float4*)&g_ssrc[row * H_HEADS] = make_float4(acc[0], acc[1], acc[2], acc[3]);
            *(float4*)&g_sdst[row * H_HEADS] = make_float4(acc[4], acc[5], acc[6], acc[7]);
        }
    }
}

// ---------------------------------------------------------------------------
// Kernel D: GEMM h16 = fp16(x) @ W16^T  (addresses hoisted, kc fully unrolled)
// ---------------------------------------------------------------------------
#define GSM_B_BYTES   32768
#define GSM_A_STAGE   8192
#define GSM_TOTAL     (GSM_B_BYTES + 3 * GSM_A_STAGE)   // 57344

__global__ __launch_bounds__(256, 3)
void gemm_kernel() {
    extern __shared__ char smem[];
    const uint32_t Bq = smem_u32(smem);
    const uint32_t Aq = Bq + GSM_B_BYTES;

    const int tid = threadIdx.x, lane = tid & 31, wid = tid >> 5;
    const int mBase = blockIdx.y * 128;
    const int nBase = blockIdx.x * 64;
    const int wm = wid >> 1;
    const int wn = wid & 1;

    // ---- B: load W n-slice (2048 x 16B chunks)
    {
#pragma unroll
        for (int i = 0; i < 8; i++) {
            int cid = i * 256 + tid;
            int n = cid >> 5;
            int c = cid & 31;
            const __half* g = &g_W16[nBase + n][c * 8];
            uint32_t s = Bq + n * 512 + ((c ^ (n & 7)) << 4);
            CP_ASYNC16(s, g);
        }
        CP_COMMIT();
    }
    // ---- A stage loader (gmem addrs hoisted: advance by 64B per stage)
    const int am = tid >> 2, ac = tid & 3;
    const __half* ag0 = g_x16 + (size_t)(mBase + am) * IN_DIM_ + ac * 8;
    const __half* ag1 = g_x16 + (size_t)(mBase + 64 + am) * IN_DIM_ + ac * 8;
    const uint32_t as0 = Aq + am * 64 + ((ac ^ ((am >> 1) & 3)) << 4);
    const uint32_t as1 = Aq + (64 + am) * 64 + ((ac ^ (((64 + am) >> 1) & 3)) << 4);
    auto loadA = [&](int kc) {
        uint32_t st = (kc % 3) * GSM_A_STAGE;
        CP_ASYNC16(as0 + st, ag0 + kc * 32);
        CP_ASYNC16(as1 + st, ag1 + kc * 32);
        CP_COMMIT();
    };
    loadA(0);
    loadA(1);
    CP_WAIT1();
    __syncthreads();

    // ---- hoisted ldmatrix addresses
    uint32_t aAddr[2][2];     // [mi][s], add stage offset at use
#pragma unroll
    for (int mi = 0; mi < 2; mi++) {
        int row = wm * 32 + mi * 16 + (lane & 15);
#pragma unroll
        for (int s = 0; s < 2; s++) {
            int c = s * 2 + (lane >> 4);
            aAddr[mi][s] = Aq + row * 64 + ((c ^ ((row >> 1) & 3)) << 4);
        }
    }
    uint32_t bAddr[2][2];     // [bi][s]: base with t-xor; add ((kc<<6)^bx[bi])
    uint32_t bx[2];
#pragma unroll
    for (int bi = 0; bi < 2; bi++) {
        int nrow = wn * 32 + bi * 16 + (lane & 15);
        bx[bi] = (nrow & 4) << 4;
#pragma unroll
        for (int s = 0; s < 2; s++) {
            int t = s * 2 + (lane >> 4);
            bAddr[bi][s] = Bq + nrow * 512 + ((t ^ (nrow & 3)) << 4);
        }
    }

    float acc[2][4][4];
#pragma unroll
    for (int mi = 0; mi < 2; mi++)
#pragma unroll
        for (int ni = 0; ni < 4; ni++)
#pragma unroll
            for (int q = 0; q < 4; q++) acc[mi][ni][q] = 0.f;

#pragma unroll
    for (int kc = 0; kc < 8; kc++) {
        const uint32_t stOff = (kc % 3) * GSM_A_STAGE;
        const uint32_t kcb = kc << 6;
#pragma unroll
        for (int s = 0; s < 2; s++) {
            uint32_t a[2][4];
#pragma unroll
            for (int mi = 0; mi < 2; mi++)
                LDMX4(a[mi][0], a[mi][1], a[mi][2], a[mi][3], aAddr[mi][s] + stOff);
            uint32_t b[4][2];
#pragma unroll
            for (int bi = 0; bi < 2; bi++) {
                uint32_t r0, r1, r2, r3;
                LDMX4(r0, r1, r2, r3, bAddr[bi][s] + (kcb ^ bx[bi]));
                b[bi * 2 + 0][0] = r0; b[bi * 2 + 0][1] = r2;
                b[bi * 2 + 1][0] = r1; b[bi * 2 + 1][1] = r3;
            }
#pragma unroll
            for (int mi = 0; mi < 2; mi++)
#pragma unroll
                for (int ni = 0; ni < 4; ni++)
                    MMA16816(acc[mi][ni], a[mi], b[ni]);
        }
        if (kc < 6) loadA(kc + 2); else CP_COMMIT();
        if (kc < 7) { CP_WAIT1(); __syncthreads(); }
    }

    // ---- epilogue
#pragma unroll
    for (int mi = 0; mi < 2; mi++)
#pragma unroll
        for (int ni = 0; ni < 4; ni++) {
            int row0 = mBase + wm * 32 + mi * 16 + (lane >> 2);
            int col  = nBase + wn * 32 + ni * 8 + (lane & 3) * 2;
            __half2 v0 = __floats2half2_rn(acc[mi][ni][0], acc[mi][ni][1]);
            __half2 v1 = __floats2half2_rn(acc[mi][ni][2], acc[mi][ni][3]);
            *(__half2*)&g_h16[(size_t)row0 * OUT_CH + col] = v0;
            *(__half2*)&g_h16[(size_t)(row0 + 8) * OUT_CH + col] = v1;
        }
}

// ---------------------------------------------------------------------------
// Kernel E: softmax + aggregation.  One warp per row.
// Lane loads uint4 = 8 halves of the gathered row (32 lanes = full 512B row).
// lane -> (head = lane>>3, outch = 8*(lane&7)+i). alpha staged via smem.
// Head-mean via shfl_xor(8,16); lanes 0-7 write 8 fp32 outputs each.
// ---------------------------------------------------------------------------
__global__ __launch_bounds__(256)
void agg_kernel(const int* __restrict__ nidx, float* __restrict__ out) {
    __shared__ float salpha[8][K_NB][H_HEADS];
    int gw   = (blockIdx.x * blockDim.x + threadIdx.x) >> 5;
    int lane = threadIdx.x & 31;
    int wid  = (threadIdx.x >> 5);
    if (gw >= M_ROWS) return;

    const int b = gw / N_NODES;
    const int k = lane & 15;
    const int j = __ldg(&nidx[gw * K_NB + k]);
    const int jr = b * N_NODES + j;
    const float scale = 0.125f;

    // scores + softmax over 16-lane group (lanes 16-31 mirror, results unused)
    float4 ssv = *(const float4*)&g_ssrc[gw * H_HEADS];
    float4 sdv = *(const float4*)&g_sdst[jr * H_HEADS];
    float e[H_HEADS] = {(ssv.x + sdv.x) * scale, (ssv.y + sdv.y) * scale,
                        (ssv.z + sdv.z) * scale, (ssv.w + sdv.w) * scale};
    float alpha[H_HEADS];
#pragma unroll
    for (int hh = 0; hh < H_HEADS; hh++) {
        float m = e[hh];
#pragma unroll
        for (int off = 8; off > 0; off >>= 1)
            m = fmaxf(m, __shfl_xor_sync(0xffffffffu, m, off));
        float ex = __expf(e[hh] - m);
        float s = ex;
#pragma unroll
        for (int off = 8; off > 0; off >>= 1)
            s += __shfl_xor_sync(0xffffffffu, s, off);
        alpha[hh] = ex / s;
    }
    if (lane < 16)
        *(float4*)&salpha[wid][lane][0] = make_float4(alpha[0], alpha[1], alpha[2], alpha[3]);
    __syncwarp();

    // gather-accumulate: lane owns 8 consecutive halves of each row
    const int myhead = lane >> 3;
    const size_t base_b = (size_t)b * N_NODES;
    float acc[8];
#pragma unroll
    for (int i = 0; i < 8; i++) acc[i] = 0.f;

#pragma unroll 4
    for (int kk = 0; kk < K_NB; kk++) {
        int jj = __shfl_sync(0xffffffffu, j, kk);
        float w = salpha[wid][kk][myhead];
        const uint4 v = *(const uint4*)(g_h16 + (base_b + (size_t)jj) * OUT_CH + lane * 8);
        const __half2* hv = (const __half2*)&v;
#pragma unroll
        for (int q = 0; q < 4; q++) {
            float2 f = __half22float2(hv[q]);
            acc[2 * q + 0] = fmaf(w, f.x, acc[2 * q + 0]);
            acc[2 * q + 1] = fmaf(w, f.y, acc[2 * q + 1]);
        }
    }

    // head reduction: lanes {l, l^8, l^16, l^24} hold heads 0..3 of same outch
#pragma unroll
    for (int i = 0; i < 8; i++) {
        acc[i] += __shfl_xor_sync(0xffffffffu, acc[i], 8);
        acc[i] += __shfl_xor_sync(0xffffffffu, acc[i], 16);
    }

    if (lane < 8) {
        float4 o0 = make_float4(acc[0] * 0.25f, acc[1] * 0.25f, acc[2] * 0.25f, acc[3] * 0.25f);
        float4 o1 = make_float4(acc[4] * 0.25f, acc[5] * 0.25f, acc[6] * 0.25f, acc[7] * 0.25f);
        float* op = out + (size_t)gw * C_HID + lane * 8;
        *(float4*)op = o0;
        *(float4*)(op + 4) = o1;
    }
}

// ---------------------------------------------------------------------------
extern "C" void kernel_launch(void* const* d_in, const int* in_sizes, int n_in,
                              void* d_out, int out_size) {
    const float* x    = (const float*)d_in[0];
    const int*   nidx = (const int*)d_in[1];
    const float* W    = (const float*)d_in[2];
    const float* attn = (const float*)d_in[3];
    float* out = (float*)d_out;

    cudaFuncSetAttribute(gemm_kernel, cudaFuncAttributeMaxDynamicSharedMemorySize, GSM_TOTAL);

    uv_kernel<<<8, 256>>>(W, attn);
    w16_kernel<<<OUT_CH, IN_DIM_>>>(W);
    xprep_kernel<<<M_ROWS / 128, 256>>>(x);
    gemm_kernel<<<dim3(4, M_ROWS / 128), 256, GSM_TOTAL>>>();
    agg_kernel<<<M_ROWS / 8, 256>>>(nidx, out);
}

// round 8
// speedup vs baseline: 2.4472x; 1.0004x over previous
#include <cuda_runtime.h>
#include <cuda_fp16.h>
#include <cstdint>

// -------------------- problem constants --------------------
#define B_DIM    4
#define N_NODES  20000
#define K_NB     16
#define IN_DIM_  256
#define C_HID    64
#define H_HEADS  4
#define M_ROWS   (B_DIM * N_NODES)     // 80000
#define OUT_CH   256                   // H*C_H
#define NTILE_M  625                   // 80000 / 128
#define NROW     111                   // persistent rows: 444 CTAs = 3/SM * 148

// -------------------- scratch (static, no allocs) --------------------
__device__ __half g_h16[(size_t)M_ROWS * OUT_CH];    // 41 MB
__device__ __half g_x16[(size_t)M_ROWS * IN_DIM_];   // 41 MB
__device__ __half g_W16[OUT_CH][IN_DIM_];
__device__ float  g_uv[8][IN_DIM_];
__device__ float  g_ssrc[M_ROWS * H_HEADS];
__device__ float  g_sdst[M_ROWS * H_HEADS];

// -------------------- asm helpers (sm_100-safe) ----------
__device__ __forceinline__ uint32_t smem_u32(const void* p) {
    uint32_t a;
    asm("{ .reg .u64 t; cvta.to.shared.u64 t, %1; cvt.u32.u64 %0, t; }" : "=r"(a) : "l"(p));
    return a;
}
#define CP_ASYNC16(saddr, gptr) \
    asm volatile("{ .reg .u64 g; cvta.to.global.u64 g, %1; cp.async.cg.shared.global [%0], [g], 16; }" \
        :: "r"(saddr), "l"(gptr) : "memory")
#define CP_COMMIT() asm volatile("cp.async.commit_group;" ::: "memory")
#define CP_WAIT1()  asm volatile("cp.async.wait_group 1;" ::: "memory")
#define LDMX4(r0, r1, r2, r3, addr) \
    asm volatile("ldmatrix.sync.aligned.m8n8.x4.shared.b16 {%0,%1,%2,%3}, [%4];" \
        : "=r"(r0), "=r"(r1), "=r"(r2), "=r"(r3) : "r"(addr))
#define MMA16816(d, a, b) \
    asm volatile("mma.sync.aligned.m16n8k16.row.col.f32.f16.f16.f32 " \
        "{%0,%1,%2,%3},{%4,%5,%6,%7},{%8,%9},{%0,%1,%2,%3};" \
        : "+f"((d)[0]), "+f"((d)[1]), "+f"((d)[2]), "+f"((d)[3]) \
        : "r"((a)[0]), "r"((a)[1]), "r"((a)[2]), "r"((a)[3]), "r"((b)[0]), "r"((b)[1]))

// ---------------------------------------------------------------------------
// Kernel A: merged prep — blocks 0..255: W->fp16 row; blocks 256..263: uv fold
// ---------------------------------------------------------------------------
__global__ void prep_kernel(const float* __restrict__ W, const float* __restrict__ attn) {
    int bid = blockIdx.x;
    int k = threadIdx.x;
    if (bid < OUT_CH) {
        g_W16[bid][k] = __float2half_rn(W[bid * IN_DIM_ + k]);
    } else {
        int t = bid - OUT_CH;          // 0..7
        int h = t & 3, side = t >> 2;
        float acc = 0.f;
#pragma unroll 8
        for (int c = 0; c < C_HID; c++)
            acc += W[(h * C_HID + c) * IN_DIM_ + k] * __ldg(&attn[h * 128 + side * C_HID + c]);
        g_uv[t][k] = acc;
    }
}

// ---------------------------------------------------------------------------
// Kernel C: x -> fp16 + fused attention scores
// ---------------------------------------------------------------------------
__global__ __launch_bounds__(256)
void xprep_kernel(const float* __restrict__ x) {
    const int tid = threadIdx.x, lane = tid & 31, wid = tid >> 5;

    float uvr[8][8];
#pragma unroll
    for (int t = 0; t < 8; t++) {
        float4 a = *(const float4*)&g_uv[t][lane * 8];
        float4 b = *(const float4*)&g_uv[t][lane * 8 + 4];
        uvr[t][0] = a.x; uvr[t][1] = a.y; uvr[t][2] = a.z; uvr[t][3] = a.w;
        uvr[t][4] = b.x; uvr[t][5] = b.y; uvr[t][6] = b.z; uvr[t][7] = b.w;
    }

    const int rowBase = (blockIdx.x * 8 + wid) * 16;
#pragma unroll 2
    for (int r = 0; r < 16; r++) {
        const int row = rowBase + r;
        const float4* xp = (const float4*)(x + (size_t)row * IN_DIM_) + lane * 2;
        float4 v0 = xp[0], v1 = xp[1];
        float xv[8] = {v0.x, v0.y, v0.z, v0.w, v1.x, v1.y, v1.z, v1.w};

        __half hh[8];
#pragma unroll
        for (int i = 0; i < 8; i++) hh[i] = __float2half_rn(xv[i]);
        *(uint4*)(g_x16 + (size_t)row * IN_DIM_ + lane * 8) = *(uint4*)hh;

        float acc[8];
#pragma unroll
        for (int t = 0; t < 8; t++) {
            float s = 0.f;
#pragma unroll
            for (int i = 0; i < 8; i++) s = fmaf(xv[i], uvr[t][i], s);
            acc[t] = s;
        }
#pragma unroll
        for (int t = 0; t < 8; t++) {
#pragma unroll
            for (int off = 16; off > 0; off >>= 1)
                acc[t] += __shfl_xor_sync(0xffffffffu, acc[t], off);
        }
        if (lane == 0) {
            *(float4*)&g_ssrc[row * H_HEADS] = make_float4(acc[0], acc[1], acc[2], acc[3]);
            *(float4*)&g_sdst[row * H_HEADS] = make_float4(acc[4], acc[5], acc[6], acc[7]);
        }
    }
}

// ---------------------------------------------------------------------------
// Kernel D: persistent GEMM. grid (4, NROW) = 444 CTAs (3/SM, single wave).
// Each CTA: B slice loaded once, loops m-tiles (by, by+111, ...) with the
// 3-stage cp.async A ring running continuously across tile boundaries.
// ---------------------------------------------------------------------------
#define GSM_B_BYTES   32768
#define GSM_A_STAGE   8192
#define GSM_TOTAL     (GSM_B_BYTES + 3 * GSM_A_STAGE)   // 57344

__global__ __launch_bounds__(256, 3)
void gemm_kernel() {
    extern __shared__ char smem[];
    const uint32_t Bq = smem_u32(smem);
    const uint32_t Aq = Bq + GSM_B_BYTES;

    const int tid = threadIdx.x, lane = tid & 31, wid = tid >> 5;
    const int nBase = blockIdx.x * 64;
    const int by = blockIdx.y;
    const int wm = wid >> 1;
    const int wn = wid & 1;

    const int ntiles = (NTILE_M - 1 - by) / NROW + 1;
    const int total = ntiles * 8;

    // ---- B: load W n-slice once (2048 x 16B chunks)
    {
#pragma unroll
        for (int i = 0; i < 8; i++) {
            int cid = i * 256 + tid;
            int n = cid >> 5;
            int c = cid & 31;
            const __half* g = &g_W16[nBase + n][c * 8];
            uint32_t s = Bq + n * 512 + ((c ^ (n & 7)) << 4);
            CP_ASYNC16(s, g);
        }
        CP_COMMIT();
    }

    // ---- A chunk loader: chunk q -> tile q>>3, kc q&7, stage q%3
    const int am = tid >> 2, ac = tid & 3;
    const uint32_t as0 = Aq + am * 64 + ((ac ^ ((am >> 1) & 3)) << 4);
    const uint32_t as1 = Aq + (64 + am) * 64 + ((ac ^ (((64 + am) >> 1) & 3)) << 4);
    auto loadQ = [&](int q) {
        int t = q >> 3, kc = q & 7;
        uint32_t st = (uint32_t)(q % 3) * GSM_A_STAGE;
        size_t mb = (size_t)(by + t * NROW) * 128;
        const __half* base = g_x16 + (mb + am) * IN_DIM_ + kc * 32 + ac * 8;
        CP_ASYNC16(as0 + st, base);
        CP_ASYNC16(as1 + st, base + (size_t)64 * IN_DIM_);
        CP_COMMIT();
    };
    loadQ(0);
    loadQ(1);
    CP_WAIT1();
    __syncthreads();

    // ---- hoisted ldmatrix addresses
    uint32_t aAddr[2][2];
#pragma unroll
    for (int mi = 0; mi < 2; mi++) {
        int row = wm * 32 + mi * 16 + (lane & 15);
#pragma unroll
        for (int s = 0; s < 2; s++) {
            int c = s * 2 + (lane >> 4);
            aAddr[mi][s] = Aq + row * 64 + ((c ^ ((row >> 1) & 3)) << 4);
        }
    }
    uint32_t bAddr[2][2], bx[2];
#pragma unroll
    for (int bi = 0; bi < 2; bi++) {
        int nrow = wn * 32 + bi * 16 + (lane & 15);
        bx[bi] = (nrow & 4) << 4;
#pragma unroll
        for (int s = 0; s < 2; s++) {
            int t = s * 2 + (lane >> 4);
            bAddr[bi][s] = Bq + nrow * 512 + ((t ^ (nrow & 3)) << 4);
        }
    }

    float acc[2][4][4];
#pragma unroll
    for (int mi = 0; mi < 2; mi++)
#pragma unroll
        for (int ni = 0; ni < 4; ni++)
#pragma unroll
            for (int q = 0; q < 4; q++) acc[mi][ni][q] = 0.f;

    int mBase = by * 128;
    int q = 0;
    uint32_t stOff = 0;
    for (int t = 0; t < ntiles; t++) {
#pragma unroll
        for (int kc = 0; kc < 8; kc++, q++) {
            const uint32_t kcb = kc << 6;
#pragma unroll
            for (int s = 0; s < 2; s++) {
                uint32_t a[2][4];
#pragma unroll
                for (int mi = 0; mi < 2; mi++)
                    LDMX4(a[mi][0], a[mi][1], a[mi][2], a[mi][3], aAddr[mi][s] + stOff);
                uint32_t b[4][2];
#pragma unroll
                for (int bi = 0; bi < 2; bi++) {
                    uint32_t r0, r1, r2, r3;
                    LDMX4(r0, r1, r2, r3, bAddr[bi][s] + (kcb ^ bx[bi]));
                    b[bi * 2 + 0][0] = r0; b[bi * 2 + 0][1] = r2;
                    b[bi * 2 + 1][0] = r1; b[bi * 2 + 1][1] = r3;
                }
#pragma unroll
                for (int mi = 0; mi < 2; mi++)
#pragma unroll
                    for (int ni = 0; ni < 4; ni++)
                        MMA16816(acc[mi][ni], a[mi], b[ni]);
            }
            if (q + 2 < total) loadQ(q + 2); else CP_COMMIT();
            if (q + 1 < total) { CP_WAIT1(); __syncthreads(); }
            stOff = (stOff == 2 * GSM_A_STAGE) ? 0 : stOff + GSM_A_STAGE;
        }

        // ---- per-tile epilogue (registers -> gmem; overlaps next prefetch)
#pragma unroll
        for (int mi = 0; mi < 2; mi++)
#pragma unroll
            for (int ni = 0; ni < 4; ni++) {
                int row0 = mBase + wm * 32 + mi * 16 + (lane >> 2);
                int col  = nBase + wn * 32 + ni * 8 + (lane & 3) * 2;
                __half2 v0 = __floats2half2_rn(acc[mi][ni][0], acc[mi][ni][1]);
                __half2 v1 = __floats2half2_rn(acc[mi][ni][2], acc[mi][ni][3]);
                *(__half2*)&g_h16[(size_t)row0 * OUT_CH + col] = v0;
                *(__half2*)&g_h16[(size_t)(row0 + 8) * OUT_CH + col] = v1;
#pragma unroll
                for (int qq = 0; qq < 4; qq++) acc[mi][ni][qq] = 0.f;
            }
        mBase += NROW * 128;
    }
}

// ---------------------------------------------------------------------------
// Kernel E: softmax + aggregation (one warp / row, uint4 gathers)
// ---------------------------------------------------------------------------
__global__ __launch_bounds__(256)
void agg_kernel(const int* __restrict__ nidx, float* __restrict__ out) {
    __shared__ float salpha[8][K_NB][H_HEADS];
    int gw   = (blockIdx.x * blockDim.x + threadIdx.x) >> 5;
    int lane = threadIdx.x & 31;
    int wid  = (threadIdx.x >> 5);
    if (gw >= M_ROWS) return;

    const int b = gw / N_NODES;
    const int k = lane & 15;
    const int j = __ldg(&nidx[gw * K_NB + k]);
    const int jr = b * N_NODES + j;
    const float scale = 0.125f;

    float4 ssv = *(const float4*)&g_ssrc[gw * H_HEADS];
    float4 sdv = *(const float4*)&g_sdst[jr * H_HEADS];
    float e[H_HEADS] = {(ssv.x + sdv.x) * scale, (ssv.y + sdv.y) * scale,
                        (ssv.z + sdv.z) * scale, (ssv.w + sdv.w) * scale};
    float alpha[H_HEADS];
#pragma unroll
    for (int hh = 0; hh < H_HEADS; hh++) {
        float m = e[hh];
#pragma unroll
        for (int off = 8; off > 0; off >>= 1)
            m = fmaxf(m, __shfl_xor_sync(0xffffffffu, m, off));
        float ex = __expf(e[hh] - m);
        float s = ex;
#pragma unroll
        for (int off = 8; off > 0; off >>= 1)
            s += __shfl_xor_sync(0xffffffffu, s, off);
        alpha[hh] = ex / s;
    }
    if (lane < 16)
        *(float4*)&salpha[wid][lane][0] = make_float4(alpha[0], alpha[1], alpha[2], alpha[3]);
    __syncwarp();

    const int myhead = lane >> 3;
    const size_t base_b = (size_t)b * N_NODES;
    float acc[8];
#pragma unroll
    for (int i = 0; i < 8; i++) acc[i] = 0.f;

#pragma unroll 4
    for (int kk = 0; kk < K_NB; kk++) {
        int jj = __shfl_sync(0xffffffffu, j, kk);
        float w = salpha[wid][kk][myhead];
        const uint4 v = *(const uint4*)(g_h16 + (base_b + (size_t)jj) * OUT_CH + lane * 8);
        const __half2* hv = (const __half2*)&v;
#pragma unroll
        for (int qq = 0; qq < 4; qq++) {
            float2 f = __half22float2(hv[qq]);
            acc[2 * qq + 0] = fmaf(w, f.x, acc[2 * qq + 0]);
            acc[2 * qq + 1] = fmaf(w, f.y, acc[2 * qq + 1]);
        }
    }

#pragma unroll
    for (int i = 0; i < 8; i++) {
        acc[i] += __shfl_xor_sync(0xffffffffu, acc[i], 8);
        acc[i] += __shfl_xor_sync(0xffffffffu, acc[i], 16);
    }

    if (lane < 8) {
        float4 o0 = make_float4(acc[0] * 0.25f, acc[1] * 0.25f, acc[2] * 0.25f, acc[3] * 0.25f);
        float4 o1 = make_float4(acc[4] * 0.25f, acc[5] * 0.25f, acc[6] * 0.25f, acc[7] * 0.25f);
        float* op = out + (size_t)gw * C_HID + lane * 8;
        *(float4*)op = o0;
        *(float4*)(op + 4) = o1;
    }
}

// ---------------------------------------------------------------------------
extern "C" void kernel_launch(void* const* d_in, const int* in_sizes, int n_in,
                              void* d_out, int out_size) {
    const float* x    = (const float*)d_in[0];
    const int*   nidx = (const int*)d_in[1];
    const float* W    = (const float*)d_in[2];
    const float* attn = (const float*)d_in[3];
    float* out = (float*)d_out;

    cudaFuncSetAttribute(gemm_kernel, cudaFuncAttributeMaxDynamicSharedMemorySize, GSM_TOTAL);

    prep_kernel<<<OUT_CH + 8, 256>>>(W, attn);
    xprep_kernel<<<M_ROWS / 128, 256>>>(x);
    gemm_kernel<<<dim3(4, NROW), 256, GSM_TOTAL>>>();
    agg_kernel<<<M_ROWS / 8, 256>>>(nidx, out);
}